// round 7
// baseline (speedup 1.0000x reference)
#include <cuda_runtime.h>
#include <math.h>

#define HH 256
#define WW 512
#define CC 16
#define ND 32
#define HW (HH * WW)
#define NDHW (ND * HW)
#define BASELINE_V 0.24f
#define WTILE 64
#define SROW 67            // padded smem row stride in float4
#define MAX_ROWS 46

__device__ __forceinline__ float iy_of(float dep, float st, float ct, float theta, float h)
{
    float dvr = atanf((dep * st + BASELINE_V) / (dep * ct)) - theta;
    float dv  = dvr * ((float)HH / 3.14159265358979323846f);
    float ypx = isfinite(dv) ? (h + dv) : 0.0f;
    return ypx * ((float)HH / ((float)HH - 1.0f)) - 0.5f;
}

// Single fused kernel.
// grid (8 wtiles, 256 h), block 256 = 16 w-groups (4 w each) x 16 d-groups (2 d each).
// Loops 4 channel-chunks; stages horizontally-interpolated y rows in smem per chunk.
__global__ __launch_bounds__(256, 4) void cv_kernel(const float* __restrict__ x,
                                                    const float* __restrict__ y,
                                                    const float* __restrict__ depth,
                                                    float* __restrict__ out)
{
    __shared__ float4 s_Z[MAX_ROWS * SROW];   // ~49 KB

    int wt    = blockIdx.x;
    int h     = blockIdx.y;
    int wg    = threadIdx.x & 15;
    int dg    = threadIdx.x >> 4;             // 0..15
    int wbase = wt * WTILE;
    int w0    = wbase + wg * 4;

    const float PI = 3.14159265358979323846f;
    float hf = (float)h;
    float theta = (hf + 0.5f) * (PI / (float)HH) - 0.5f * PI;
    float st, ct;
    sincosf(theta, &st, &ct);

    // row range needed by all depths in [0.5, 8] at this h (iy monotone decr. in depth)
    float iy_min = iy_of(8.0f, st, ct, theta, hf);
    float iy_max = iy_of(0.5f, st, ct, theta, hf);
    int r_lo = min(max((int)floorf(iy_min) - 1, 0), HH - 1);
    int r_hi = min(max((int)floorf(iy_max) + 2, 0), HH - 1);
    int nrows = min(r_hi - r_lo + 1, MAX_ROWS);

    // ---- per-thread vertical interp params: chunk-invariant, precompute ----
    int hw0 = h * WW + w0;
    float wA[2][4], wB[2][4];
    int   o0[2][4], o1[2][4];    // smem float4 indices
    #pragma unroll
    for (int k = 0; k < 2; k++) {
        int d = dg * 2 + k;
        float4 dep = *(const float4*)(depth + (size_t)d * HW + hw0);
        #pragma unroll
        for (int j = 0; j < 4; j++) {
            float dv = (j == 0) ? dep.x : (j == 1) ? dep.y : (j == 2) ? dep.z : dep.w;
            float iy = iy_of(dv, st, ct, theta, hf);
            float fy0 = floorf(iy);
            float wy  = iy - fy0;
            int yi0 = (int)fy0, yi1 = yi0 + 1;
            wA[k][j] = (yi0 >= 0 && yi0 < HH) ? (1.0f - wy) : 0.0f;
            wB[k][j] = (yi1 >= 0 && yi1 < HH) ? wy : 0.0f;
            int yc0 = min(max(yi0, 0), HH - 1);
            int yc1 = min(max(yi1, 0), HH - 1);
            int ry0 = min(max(yc0 - r_lo, 0), nrows - 1);
            int ry1 = min(max(yc1 - r_lo, 0), nrows - 1);
            o0[k][j] = ry0 * SROW + wg * 4 + j;
            o1[k][j] = ry1 * SROW + wg * 4 + j;
        }
    }

    // ---- chunk loop ----
    for (int chunk = 0; chunk < 4; chunk++) {
        int c0 = chunk * 4;
        if (chunk > 0) __syncthreads();   // previous chunk's reads done

        // stage: horizontal interp of y rows [r_lo, r_lo+nrows) for this wtile
        for (int i = threadIdx.x; i < nrows * WTILE; i += 256) {
            int row = i >> 6;
            int col = i & (WTILE - 1);
            int wp  = wbase + col;
            float ix = (float)wp * ((float)WW / ((float)WW - 1.0f)) - 0.5f;
            float fx0 = floorf(ix);
            float wx  = ix - fx0;
            int xi0 = (int)fx0, xi1 = xi0 + 1;
            float w0x = (xi0 >= 0 && xi0 < WW) ? (1.0f - wx) : 0.0f;
            float w1x = (xi1 >= 0 && xi1 < WW) ? wx : 0.0f;
            int xc0 = min(max(xi0, 0), WW - 1);
            int xc1 = min(max(xi1, 0), WW - 1);
            int rb  = (r_lo + row) * WW;
            float v[4];
            #pragma unroll
            for (int c = 0; c < 4; c++) {
                const float* yc = y + (size_t)(c0 + c) * HW + rb;
                v[c] = w0x * __ldg(yc + xc0) + w1x * __ldg(yc + xc1);
            }
            s_Z[row * SROW + col] = make_float4(v[0], v[1], v[2], v[3]);
        }

        // x values for this chunk (vector loads, d-invariant)
        float4 xv0 = *(const float4*)(x + (size_t)(c0 + 0) * HW + hw0);
        float4 xv1 = *(const float4*)(x + (size_t)(c0 + 1) * HW + hw0);
        float4 xv2 = *(const float4*)(x + (size_t)(c0 + 2) * HW + hw0);
        float4 xv3 = *(const float4*)(x + (size_t)(c0 + 3) * HW + hw0);

        __syncthreads();

        #pragma unroll
        for (int k = 0; k < 2; k++) {
            int d = dg * 2 + k;
            float oc[4][4];
            #pragma unroll
            for (int j = 0; j < 4; j++) {
                float4 a = s_Z[o0[k][j]];
                float4 b = s_Z[o1[k][j]];
                float fA = wA[k][j], fB = wB[k][j];
                oc[0][j] = fmaf(fA, a.x, fB * b.x);
                oc[1][j] = fmaf(fA, a.y, fB * b.y);
                oc[2][j] = fmaf(fA, a.z, fB * b.z);
                oc[3][j] = fmaf(fA, a.w, fB * b.w);
            }
            size_t base = (size_t)d * HW + hw0;
            float* oy = out + (size_t)(CC + c0) * NDHW + base;
            float* ox = out + (size_t)c0 * NDHW + base;
            __stcs((float4*)(oy + 0 * (size_t)NDHW), make_float4(oc[0][0], oc[0][1], oc[0][2], oc[0][3]));
            __stcs((float4*)(oy + 1 * (size_t)NDHW), make_float4(oc[1][0], oc[1][1], oc[1][2], oc[1][3]));
            __stcs((float4*)(oy + 2 * (size_t)NDHW), make_float4(oc[2][0], oc[2][1], oc[2][2], oc[2][3]));
            __stcs((float4*)(oy + 3 * (size_t)NDHW), make_float4(oc[3][0], oc[3][1], oc[3][2], oc[3][3]));
            __stcs((float4*)(ox + 0 * (size_t)NDHW), xv0);
            __stcs((float4*)(ox + 1 * (size_t)NDHW), xv1);
            __stcs((float4*)(ox + 2 * (size_t)NDHW), xv2);
            __stcs((float4*)(ox + 3 * (size_t)NDHW), xv3);
        }
    }
}

extern "C" void kernel_launch(void* const* d_in, const int* in_sizes, int n_in,
                              void* d_out, int out_size) {
    const float* x     = (const float*)d_in[0];
    const float* y     = (const float*)d_in[1];
    const float* depth = (const float*)d_in[2];
    float* out = (float*)d_out;

    dim3 grid(WW / WTILE, HH);   // 8 x 256
    cv_kernel<<<grid, 256>>>(x, y, depth, out);
}

// round 8
// speedup vs baseline: 1.2411x; 1.2411x over previous
#include <cuda_runtime.h>
#include <math.h>

#define HH 256
#define WW 512
#define CC 16
#define ND 32
#define HW (HH * WW)
#define NDHW (ND * HW)
#define BASELINE_V 0.24f
#define WTILE 32
#define SROW 33            // padded smem row stride in float4
#define MAX_ROWS 46

// Horizontally pre-interpolated y, 4 channel-chunk planes
__device__ float4 g_Z[4 * HW];
// Precomputed vertical sample position per (d,h,w)
__device__ float g_iy[NDHW];

__device__ __forceinline__ float iy_of(float dep, float st, float ct, float theta, float h)
{
    float dvr = atanf((dep * st + BASELINE_V) / (dep * ct)) - theta;
    float dv  = dvr * ((float)HH / 3.14159265358979323846f);
    float ypx = isfinite(dv) ? (h + dv) : 0.0f;
    return ypx * ((float)HH / ((float)HH - 1.0f)) - 0.5f;
}

// ---------------- Kernel 1: merged prologue (hinterp + iy) ----------------
__global__ __launch_bounds__(256) void prologue_kernel(const float* __restrict__ y,
                                                       const float* __restrict__ depth)
{
    int p = blockIdx.x * 256 + threadIdx.x;   // HW threads
    int w = p & (WW - 1);
    int h = p >> 9;
    int rbase = p - w;

    const float PI = 3.14159265358979323846f;
    float hf = (float)h;
    float theta = (hf + 0.5f) * (PI / (float)HH) - 0.5f * PI;
    float st, ct;
    sincosf(theta, &st, &ct);

    // --- horizontal interp of y into 4 chunk planes ---
    float ix = (float)w * ((float)WW / ((float)WW - 1.0f)) - 0.5f;
    float fx0 = floorf(ix);
    float wx  = ix - fx0;
    int xi0 = (int)fx0, xi1 = xi0 + 1;
    float w0x = (xi0 >= 0 && xi0 < WW) ? (1.0f - wx) : 0.0f;
    float w1x = (xi1 >= 0 && xi1 < WW) ? wx : 0.0f;
    int xc0 = min(max(xi0, 0), WW - 1);
    int xc1 = min(max(xi1, 0), WW - 1);

    #pragma unroll
    for (int chunk = 0; chunk < 4; chunk++) {
        float v[4];
        #pragma unroll
        for (int c = 0; c < 4; c++) {
            const float* yc = y + (size_t)(chunk * 4 + c) * HW + rbase;
            v[c] = w0x * __ldg(yc + xc0) + w1x * __ldg(yc + xc1);
        }
        g_Z[chunk * HW + p] = make_float4(v[0], v[1], v[2], v[3]);
    }

    // --- vertical sample positions for all 32 disparities at this pixel ---
    #pragma unroll 4
    for (int d = 0; d < ND; d++) {
        float dep = __ldg(depth + (size_t)d * HW + p);
        g_iy[(size_t)d * HW + p] = iy_of(dep, st, ct, theta, hf);
    }
}

// ---------------- Kernel 2: smem-staged fused kernel ----------------
// grid (4 chunks * 16 wtiles, HH). Block 256: wg=tid&7 (4 w each), d=tid>>3 (one d).
__global__ __launch_bounds__(256, 6) void fused_cv_kernel(const float* __restrict__ x,
                                                          float* __restrict__ out)
{
    __shared__ float4 s_Z[MAX_ROWS * SROW];   // ~24.3 KB

    int chunk = blockIdx.x & 3;
    int wt    = blockIdx.x >> 2;
    int h     = blockIdx.y;
    int wg    = threadIdx.x & 7;
    int d     = threadIdx.x >> 3;             // 0..31
    int wbase = wt * WTILE;
    int w0    = wbase + wg * 4;
    int c0    = chunk * 4;

    const float PI = 3.14159265358979323846f;
    float hf = (float)h;
    float theta = (hf + 0.5f) * (PI / (float)HH) - 0.5f * PI;
    float st, ct;
    sincosf(theta, &st, &ct);

    // row range for all depths in [0.5, 8] at this h (iy monotone decr. in depth)
    float iy_min = iy_of(8.0f, st, ct, theta, hf);
    float iy_max = iy_of(0.5f, st, ct, theta, hf);
    int r_lo = min(max((int)floorf(iy_min) - 1, 0), HH - 1);
    int r_hi = min(max((int)floorf(iy_max) + 2, 0), HH - 1);
    int nrows = min(r_hi - r_lo + 1, MAX_ROWS);

    // cooperative staging of Z rows for this wtile
    const float4* __restrict__ plane = g_Z + (size_t)chunk * HW;
    for (int i = threadIdx.x; i < nrows * WTILE; i += 256) {
        int row = i >> 5;
        int col = i & (WTILE - 1);
        s_Z[row * SROW + col] = __ldg(plane + (size_t)(r_lo + row) * WW + wbase + col);
    }

    // vertical interp params for my 4 w at my d
    int hw0 = h * WW + w0;
    float4 iy4 = *(const float4*)(g_iy + (size_t)d * HW + hw0);
    float wA[4], wB[4];
    int   o0[4], o1[4];
    #pragma unroll
    for (int j = 0; j < 4; j++) {
        float iy = (j == 0) ? iy4.x : (j == 1) ? iy4.y : (j == 2) ? iy4.z : iy4.w;
        float fy0 = floorf(iy);
        float wy  = iy - fy0;
        int yi0 = (int)fy0, yi1 = yi0 + 1;
        wA[j] = (yi0 >= 0 && yi0 < HH) ? (1.0f - wy) : 0.0f;
        wB[j] = (yi1 >= 0 && yi1 < HH) ? wy : 0.0f;
        int yc0 = min(max(yi0, 0), HH - 1);
        int yc1 = min(max(yi1, 0), HH - 1);
        int ry0 = min(max(yc0 - r_lo, 0), nrows - 1);
        int ry1 = min(max(yc1 - r_lo, 0), nrows - 1);
        o0[j] = ry0 * SROW + wg * 4 + j;
        o1[j] = ry1 * SROW + wg * 4 + j;
    }

    __syncthreads();

    // gather + vertical interp: 8 LDS.128 -> 16 outputs
    float oc[4][4];
    #pragma unroll
    for (int j = 0; j < 4; j++) {
        float4 a = s_Z[o0[j]];
        float4 b = s_Z[o1[j]];
        float fA = wA[j], fB = wB[j];
        oc[0][j] = fmaf(fA, a.x, fB * b.x);
        oc[1][j] = fmaf(fA, a.y, fB * b.y);
        oc[2][j] = fmaf(fA, a.z, fB * b.z);
        oc[3][j] = fmaf(fA, a.w, fB * b.w);
    }

    size_t base = (size_t)d * HW + hw0;
    float* oy = out + (size_t)(CC + c0) * NDHW + base;
    float* ox = out + (size_t)c0 * NDHW + base;

    __stcs((float4*)(oy + 0 * (size_t)NDHW), make_float4(oc[0][0], oc[0][1], oc[0][2], oc[0][3]));
    __stcs((float4*)(oy + 1 * (size_t)NDHW), make_float4(oc[1][0], oc[1][1], oc[1][2], oc[1][3]));
    __stcs((float4*)(oy + 2 * (size_t)NDHW), make_float4(oc[2][0], oc[2][1], oc[2][2], oc[2][3]));
    __stcs((float4*)(oy + 3 * (size_t)NDHW), make_float4(oc[3][0], oc[3][1], oc[3][2], oc[3][3]));

    #pragma unroll
    for (int c = 0; c < 4; c++) {
        float4 xv = *(const float4*)(x + (size_t)(c0 + c) * HW + hw0);
        __stcs((float4*)(ox + (size_t)c * NDHW), xv);
    }
}

extern "C" void kernel_launch(void* const* d_in, const int* in_sizes, int n_in,
                              void* d_out, int out_size) {
    const float* x     = (const float*)d_in[0];
    const float* y     = (const float*)d_in[1];
    const float* depth = (const float*)d_in[2];
    float* out = (float*)d_out;

    prologue_kernel<<<HW / 256, 256>>>(y, depth);
    dim3 grid(4 * (WW / WTILE), HH);   // chunk fastest
    fused_cv_kernel<<<grid, 256>>>(x, out);
}

// round 9
// speedup vs baseline: 1.3616x; 1.0971x over previous
#include <cuda_runtime.h>
#include <math.h>

#define HH 256
#define WW 512
#define CC 16
#define ND 32
#define HW (HH * WW)
#define NDHW (ND * HW)
#define BASELINE_V 0.24f
#define WTILE 64
#define SROW 67            // padded smem row stride in float4
#define MAX_ROWS 46

// Horizontally pre-interpolated y, 4 channel-chunk planes
__device__ float4 g_Z[4 * HW];
// Precomputed vertical sample position per (d,h,w)
__device__ float g_iy[NDHW];

// iy via cancellation-free identity: atan(u) - theta = atan(B*cos/(d + B*sin))
__device__ __forceinline__ float iy_fast(float dep, float Bs, float Bc, float hf)
{
    float dth = atanf(Bc / (dep + Bs));                      // > 0, small arg
    float ypx = hf + dth * ((float)HH / 3.14159265358979323846f);
    return ypx * ((float)HH / ((float)HH - 1.0f)) - 0.5f;
}

// ---------------- Kernel 1: horizontal interp, thread = (chunk, pixel) ----------------
__global__ __launch_bounds__(256) void hinterp_kernel(const float* __restrict__ y)
{
    int t = blockIdx.x * 256 + threadIdx.x;   // 4*HW threads
    int p = t & (HW - 1);
    int chunk = t >> 17;
    int w = p & (WW - 1);
    int rbase = p - w;

    float ix = (float)w * ((float)WW / ((float)WW - 1.0f)) - 0.5f;
    float fx0 = floorf(ix);
    float wx  = ix - fx0;
    int xi0 = (int)fx0, xi1 = xi0 + 1;
    float w0x = (xi0 >= 0 && xi0 < WW) ? (1.0f - wx) : 0.0f;
    float w1x = (xi1 >= 0 && xi1 < WW) ? wx : 0.0f;
    int xc0 = min(max(xi0, 0), WW - 1);
    int xc1 = min(max(xi1, 0), WW - 1);

    float v[4];
    #pragma unroll
    for (int c = 0; c < 4; c++) {
        const float* yc = y + (size_t)(chunk * 4 + c) * HW + rbase;
        v[c] = w0x * __ldg(yc + xc0) + w1x * __ldg(yc + xc1);
    }
    g_Z[chunk * HW + p] = make_float4(v[0], v[1], v[2], v[3]);
}

// ---------------- Kernel 2: iy per (d,h,w), vectorized ----------------
__global__ __launch_bounds__(256) void iy_kernel(const float* __restrict__ depth)
{
    int idx = blockIdx.x * 256 + threadIdx.x;   // NDHW/4 threads
    int h = (idx >> 7) & (HH - 1);              // 4 consecutive elems share h

    const float PI = 3.14159265358979323846f;
    float hf = (float)h;
    float theta = (hf + 0.5f) * (PI / (float)HH) - 0.5f * PI;
    float st, ct;
    sincosf(theta, &st, &ct);
    float Bs = BASELINE_V * st, Bc = BASELINE_V * ct;

    float4 dep = ((const float4*)depth)[idx];
    float4 r;
    r.x = iy_fast(dep.x, Bs, Bc, hf);
    r.y = iy_fast(dep.y, Bs, Bc, hf);
    r.z = iy_fast(dep.z, Bs, Bc, hf);
    r.w = iy_fast(dep.w, Bs, Bc, hf);
    ((float4*)g_iy)[idx] = r;
}

// ---------------- Kernel 3: smem-staged fused kernel (R6 config) ----------------
// grid (4 chunks * 8 wtiles, HH). Block 256 = 16 wg (4 w) x 16 dg (2 d each).
__global__ __launch_bounds__(256, 4) void fused_cv_kernel(const float* __restrict__ x,
                                                          float* __restrict__ out)
{
    __shared__ float4 s_Z[MAX_ROWS * SROW];   // ~49.3 KB

    int chunk = blockIdx.x & 3;
    int wt    = blockIdx.x >> 2;
    int h     = blockIdx.y;
    int wg    = threadIdx.x & 15;
    int dg    = threadIdx.x >> 4;              // 0..15
    int wbase = wt * WTILE;
    int w0    = wbase + wg * 4;
    int c0    = chunk * 4;

    const float PI = 3.14159265358979323846f;
    float hf = (float)h;
    float theta = (hf + 0.5f) * (PI / (float)HH) - 0.5f * PI;
    float st, ct;
    sincosf(theta, &st, &ct);
    float Bs = BASELINE_V * st, Bc = BASELINE_V * ct;

    // row range for depth in [0.5, 8] (iy monotone decreasing in depth)
    float iy_min = iy_fast(8.0f, Bs, Bc, hf);
    float iy_max = iy_fast(0.5f, Bs, Bc, hf);
    int r_lo = min(max((int)floorf(iy_min) - 1, 0), HH - 1);
    int r_hi = min(max((int)floorf(iy_max) + 2, 0), HH - 1);
    int nrows = min(r_hi - r_lo + 1, MAX_ROWS);

    int hw0 = h * WW + w0;

    // prefetch iy for both d's (latency overlaps with staging below)
    float4 iy4_0 = *(const float4*)(g_iy + (size_t)(dg * 2 + 0) * HW + hw0);
    float4 iy4_1 = *(const float4*)(g_iy + (size_t)(dg * 2 + 1) * HW + hw0);

    // cooperative staging of Z rows for this wtile
    const float4* __restrict__ plane = g_Z + (size_t)chunk * HW;
    for (int i = threadIdx.x; i < nrows * WTILE; i += 256) {
        int row = i >> 6;
        int col = i & (WTILE - 1);
        s_Z[row * SROW + col] = __ldg(plane + (size_t)(r_lo + row) * WW + wbase + col);
    }

    // vertical interp params (ALU overlaps other warps' staging)
    float wA[2][4], wB[2][4];
    int   o0[2][4], o1[2][4];
    #pragma unroll
    for (int k = 0; k < 2; k++) {
        float4 iy4 = k ? iy4_1 : iy4_0;
        #pragma unroll
        for (int j = 0; j < 4; j++) {
            float iy = (j == 0) ? iy4.x : (j == 1) ? iy4.y : (j == 2) ? iy4.z : iy4.w;
            float fy0 = floorf(iy);
            float wy  = iy - fy0;
            int yi0 = (int)fy0, yi1 = yi0 + 1;
            wA[k][j] = (yi0 >= 0 && yi0 < HH) ? (1.0f - wy) : 0.0f;
            wB[k][j] = (yi1 >= 0 && yi1 < HH) ? wy : 0.0f;
            int yc0 = min(max(yi0, 0), HH - 1);
            int yc1 = min(max(yi1, 0), HH - 1);
            int ry0 = min(max(yc0 - r_lo, 0), nrows - 1);
            int ry1 = min(max(yc1 - r_lo, 0), nrows - 1);
            o0[k][j] = ry0 * SROW + wg * 4 + j;
            o1[k][j] = ry1 * SROW + wg * 4 + j;
        }
    }

    __syncthreads();

    #pragma unroll
    for (int k = 0; k < 2; k++) {
        int d = dg * 2 + k;
        float oc[4][4];
        #pragma unroll
        for (int j = 0; j < 4; j++) {
            float4 a = s_Z[o0[k][j]];
            float4 b = s_Z[o1[k][j]];
            float fA = wA[k][j], fB = wB[k][j];
            oc[0][j] = fmaf(fA, a.x, fB * b.x);
            oc[1][j] = fmaf(fA, a.y, fB * b.y);
            oc[2][j] = fmaf(fA, a.z, fB * b.z);
            oc[3][j] = fmaf(fA, a.w, fB * b.w);
        }
        size_t base = (size_t)d * HW + hw0;
        float* oy = out + (size_t)(CC + c0) * NDHW + base;
        float* ox = out + (size_t)c0 * NDHW + base;
        __stcs((float4*)(oy + 0 * (size_t)NDHW), make_float4(oc[0][0], oc[0][1], oc[0][2], oc[0][3]));
        __stcs((float4*)(oy + 1 * (size_t)NDHW), make_float4(oc[1][0], oc[1][1], oc[1][2], oc[1][3]));
        __stcs((float4*)(oy + 2 * (size_t)NDHW), make_float4(oc[2][0], oc[2][1], oc[2][2], oc[2][3]));
        __stcs((float4*)(oy + 3 * (size_t)NDHW), make_float4(oc[3][0], oc[3][1], oc[3][2], oc[3][3]));
        #pragma unroll
        for (int c = 0; c < 4; c++) {
            float4 xv = *(const float4*)(x + (size_t)(c0 + c) * HW + hw0);
            __stcs((float4*)(ox + (size_t)c * NDHW), xv);
        }
    }
}

extern "C" void kernel_launch(void* const* d_in, const int* in_sizes, int n_in,
                              void* d_out, int out_size) {
    const float* x     = (const float*)d_in[0];
    const float* y     = (const float*)d_in[1];
    const float* depth = (const float*)d_in[2];
    float* out = (float*)d_out;

    hinterp_kernel<<<(4 * HW) / 256, 256>>>(y);
    iy_kernel<<<(NDHW / 4) / 256, 256>>>(depth);
    dim3 grid(4 * (WW / WTILE), HH);   // chunk fastest
    fused_cv_kernel<<<grid, 256>>>(x, out);
}